// round 3
// baseline (speedup 1.0000x reference)
#include <cuda_runtime.h>
#include <math.h>

// ---------------------------------------------------------------------------
// TimeSformer forward, fp32. B=2, T=8, N=196, C=768, H=12, hd=64, depth=12.
// ---------------------------------------------------------------------------

constexpr int BATCH = 2;
constexpr int TT    = 8;
constexpr int NP    = 196;
constexpr int CD    = 768;
constexpr int NH    = 12;
constexpr int HD    = 64;
constexpr int SEQ   = 1 + TT * NP;          // 1569
constexpr int RT    = BATCH * TT * NP;      // 3136 rows (time-attn view)
constexpr int KS    = NP + 1;               // 197
constexpr int RS    = BATCH * TT * KS;      // 3152 rows (space-attn view)
constexpr int RX    = BATCH * SEQ;          // 3138 rows (full stream)
constexpr int GROUPS= BATCH * TT * NH;      // 192 attention groups
constexpr int DEPTH = 12;

// -------------------------- scratch (device globals) -----------------------
__device__ float g_xb     [(size_t)BATCH * SEQ * CD];
__device__ float g_patches[(size_t)RT * CD];
__device__ float g_buf1   [(size_t)RS * CD];
__device__ float g_buf2   [(size_t)RS * CD];
__device__ float g_buf3   [(size_t)RS * CD];
__device__ float g_attno  [(size_t)RS * CD];
__device__ float g_qkv    [(size_t)RS * 3 * CD];
__device__ float g_scores [(size_t)GROUPS * KS * KS];
__device__ float g_fc1    [(size_t)RX * 4 * CD];

// ------------------------------- SGEMM --------------------------------------
// C[m,n] = sum_k A[m,k]*W[n,k] + bias[n]   (A: MxK rm, W: NxK rm, C: MxN rm)
// act==1 -> exact GELU epilogue.
__global__ void __launch_bounds__(256) sgemm_kernel(
    const float* __restrict__ A, const float* __restrict__ W,
    const float* __restrict__ bias, float* __restrict__ C,
    int M, int N, int K, int act)
{
    __shared__ float As[8][128];
    __shared__ float Ws[8][128];
    const int tid = threadIdx.x;
    const int tx  = tid & 15;        // 0..15
    const int ty  = tid >> 4;        // 0..15
    const int row0 = blockIdx.y * 128;
    const int col0 = blockIdx.x * 128;

    float acc[8][8];
    #pragma unroll
    for (int i = 0; i < 8; i++)
        #pragma unroll
        for (int j = 0; j < 8; j++) acc[i][j] = 0.f;

    const int lr = tid >> 1;         // 0..127
    const int lc = (tid & 1) * 4;    // 0 or 4
    const float* Ap = A + (size_t)(row0 + lr) * K + lc;
    const float* Wp = W + (size_t)(col0 + lr) * K + lc;
    const bool av = (row0 + lr) < M;
    const bool wv = (col0 + lr) < N;

    for (int k0 = 0; k0 < K; k0 += 8) {
        float4 a4 = av ? *(const float4*)(Ap + k0) : make_float4(0.f, 0.f, 0.f, 0.f);
        float4 w4 = wv ? *(const float4*)(Wp + k0) : make_float4(0.f, 0.f, 0.f, 0.f);
        __syncthreads();
        As[lc + 0][lr] = a4.x; As[lc + 1][lr] = a4.y;
        As[lc + 2][lr] = a4.z; As[lc + 3][lr] = a4.w;
        Ws[lc + 0][lr] = w4.x; Ws[lc + 1][lr] = w4.y;
        Ws[lc + 2][lr] = w4.z; Ws[lc + 3][lr] = w4.w;
        __syncthreads();
        #pragma unroll
        for (int kk = 0; kk < 8; kk++) {
            float ar[8], br[8];
            #pragma unroll
            for (int i = 0; i < 8; i++) ar[i] = As[kk][ty + 16 * i];
            #pragma unroll
            for (int j = 0; j < 8; j++) br[j] = Ws[kk][tx + 16 * j];
            #pragma unroll
            for (int i = 0; i < 8; i++)
                #pragma unroll
                for (int j = 0; j < 8; j++)
                    acc[i][j] = fmaf(ar[i], br[j], acc[i][j]);
        }
    }

    #pragma unroll
    for (int i = 0; i < 8; i++) {
        int r = row0 + ty + 16 * i;
        if (r >= M) continue;
        #pragma unroll
        for (int j = 0; j < 8; j++) {
            int c = col0 + tx + 16 * j;
            if (c >= N) continue;
            float v = acc[i][j] + bias[c];
            if (act) v = v * normcdff(v);   // exact GELU: x*Phi(x)
            C[(size_t)r * N + c] = v;
        }
    }
}

// ------------------------------ LayerNorm -----------------------------------
__device__ __forceinline__ float blk_sum(float v, float* sm)
{
    const int lane = threadIdx.x & 31, w = threadIdx.x >> 5;
    #pragma unroll
    for (int o = 16; o; o >>= 1) v += __shfl_xor_sync(0xffffffffu, v, o);
    if (lane == 0) sm[w] = v;
    __syncthreads();
    if (threadIdx.x == 0) {
        float t = 0.f;
        #pragma unroll
        for (int i = 0; i < 8; i++) t += sm[i];
        sm[8] = t;
    }
    __syncthreads();
    float t = sm[8];
    __syncthreads();
    return t;
}

__global__ void __launch_bounds__(256) ln_kernel(
    const float* __restrict__ in, float* __restrict__ out,
    const float* __restrict__ w, const float* __restrict__ b)
{
    __shared__ float sm[9];
    const size_t r = blockIdx.x;
    const float* x = in + r * CD;
    const int t = threadIdx.x;
    float v0 = x[t], v1 = x[t + 256], v2 = x[t + 512];
    float tot = blk_sum(v0 + v1 + v2, sm);
    float mean = tot * (1.0f / CD);
    float d0 = v0 - mean, d1 = v1 - mean, d2 = v2 - mean;
    float tot2 = blk_sum(d0 * d0 + d1 * d1 + d2 * d2, sm);
    float inv = rsqrtf(tot2 * (1.0f / CD) + 1e-6f);
    float* o = out + r * CD;
    o[t]       = d0 * inv * w[t]       + b[t];
    o[t + 256] = d1 * inv * w[t + 256] + b[t + 256];
    o[t + 512] = d2 * inv * w[t + 512] + b[t + 512];
}

// ------------------------- Time attention (seq=8) ---------------------------
__global__ void __launch_bounds__(64) time_attn_kernel()
{
    const int g = blockIdx.x;          // 0..4703
    const int h = g % NH;
    const int bn = g / NH;             // 0..391
    const int lane = threadIdx.x;      // 0..63
    __shared__ float Q[TT][HD + 1], Kk[TT][HD + 1], V[TT][HD + 1];
    __shared__ float P[TT][TT + 1];
    #pragma unroll
    for (int t = 0; t < TT; t++) {
        size_t base = ((size_t)(bn * TT + t)) * (3 * CD) + h * HD + lane;
        Q[t][lane]  = g_qkv[base];
        Kk[t][lane] = g_qkv[base + CD];
        V[t][lane]  = g_qkv[base + 2 * CD];
    }
    __syncthreads();
    const int tq = lane >> 3, tk = lane & 7;
    float s = 0.f;
    #pragma unroll
    for (int d = 0; d < HD; d++) s += Q[tq][d] * Kk[tk][d];
    P[tq][tk] = s * 0.125f;
    __syncthreads();
    if (lane < TT) {
        float m = -1e30f;
        #pragma unroll
        for (int k = 0; k < TT; k++) m = fmaxf(m, P[lane][k]);
        float sum = 0.f;
        #pragma unroll
        for (int k = 0; k < TT; k++) { float e = expf(P[lane][k] - m); P[lane][k] = e; sum += e; }
        float inv = 1.f / sum;
        #pragma unroll
        for (int k = 0; k < TT; k++) P[lane][k] *= inv;
    }
    __syncthreads();
    #pragma unroll
    for (int t = 0; t < TT; t++) {
        float a = 0.f;
        #pragma unroll
        for (int k = 0; k < TT; k++) a += P[t][k] * V[k][lane];
        g_attno[((size_t)(bn * TT + t)) * CD + h * HD + lane] = a;
    }
}

// ------------------------- Space attention (seq=197) ------------------------
__global__ void __launch_bounds__(256) space_scores_kernel()
{
    const int g = blockIdx.x;                 // bt*12+h
    const int h = g % NH, bt = g / NH;
    const int q0 = blockIdx.y * 32, k0 = blockIdx.z * 64;
    __shared__ float Qs[32][HD + 1];
    __shared__ float Ksm[64][HD + 1];
    const int tid = threadIdx.x;
    for (int i = tid; i < 32 * 64; i += 256) {
        int r = i >> 6, d = i & 63; int gq = q0 + r;
        Qs[r][d] = (gq < KS) ? g_qkv[((size_t)(bt * KS + gq)) * (3 * CD) + h * HD + d] : 0.f;
    }
    for (int i = tid; i < 64 * 64; i += 256) {
        int r = i >> 6, d = i & 63; int gk = k0 + r;
        Ksm[r][d] = (gk < KS) ? g_qkv[((size_t)(bt * KS + gk)) * (3 * CD) + CD + h * HD + d] : 0.f;
    }
    __syncthreads();
    const int kc = tid & 63, qb = tid >> 6;
    float s[8];
    #pragma unroll
    for (int i = 0; i < 8; i++) s[i] = 0.f;
    #pragma unroll
    for (int d = 0; d < HD; d++) {
        float kv = Ksm[kc][d];
        #pragma unroll
        for (int i = 0; i < 8; i++) s[i] = fmaf(Qs[qb + 4 * i][d], kv, s[i]);
    }
    const int gk = k0 + kc;
    if (gk < KS) {
        #pragma unroll
        for (int i = 0; i < 8; i++) {
            int gq = q0 + qb + 4 * i;
            if (gq < KS) g_scores[((size_t)g * KS + gq) * KS + gk] = s[i] * 0.125f;
        }
    }
}

__global__ void __launch_bounds__(32) softmax197_kernel()
{
    const size_t row = blockIdx.x;        // GROUPS*KS rows
    float* p = g_scores + row * KS;
    const int lane = threadIdx.x;
    float vals[7];
    float m = -1e30f;
    #pragma unroll
    for (int i = 0; i < 7; i++) {
        int j = lane + 32 * i;
        vals[i] = (j < KS) ? p[j] : -1e30f;
        m = fmaxf(m, vals[i]);
    }
    #pragma unroll
    for (int o = 16; o; o >>= 1) m = fmaxf(m, __shfl_xor_sync(0xffffffffu, m, o));
    float s = 0.f;
    #pragma unroll
    for (int i = 0; i < 7; i++) {
        int j = lane + 32 * i;
        if (j < KS) { vals[i] = expf(vals[i] - m); s += vals[i]; }
    }
    #pragma unroll
    for (int o = 16; o; o >>= 1) s += __shfl_xor_sync(0xffffffffu, s, o);
    float inv = 1.f / s;
    #pragma unroll
    for (int i = 0; i < 7; i++) {
        int j = lane + 32 * i;
        if (j < KS) p[j] = vals[i] * inv;
    }
}

__global__ void __launch_bounds__(256) space_pv_kernel()
{
    const int g = blockIdx.x;
    const int h = g % NH, bt = g / NH;
    const int q0 = blockIdx.y * 32;
    __shared__ float Ps[32][33];
    __shared__ float Vs[32][HD + 1];
    const int tid = threadIdx.x;
    const int dc = tid & 63, qb = tid >> 6;
    float acc[8];
    #pragma unroll
    for (int i = 0; i < 8; i++) acc[i] = 0.f;
    for (int c0 = 0; c0 < KS; c0 += 32) {
        for (int i = tid; i < 32 * 32; i += 256) {
            int r = i >> 5, c = i & 31; int gq = q0 + r, gk = c0 + c;
            Ps[r][c] = (gq < KS && gk < KS) ? g_scores[((size_t)g * KS + gq) * KS + gk] : 0.f;
        }
        for (int i = tid; i < 32 * 64; i += 256) {
            int r = i >> 6, d = i & 63; int gk = c0 + r;
            Vs[r][d] = (gk < KS) ? g_qkv[((size_t)(bt * KS + gk)) * (3 * CD) + 2 * CD + h * HD + d] : 0.f;
        }
        __syncthreads();
        #pragma unroll
        for (int kk = 0; kk < 32; kk++) {
            float vv = Vs[kk][dc];
            #pragma unroll
            for (int i = 0; i < 8; i++) acc[i] = fmaf(Ps[qb + 4 * i][kk], vv, acc[i]);
        }
        __syncthreads();
    }
    #pragma unroll
    for (int i = 0; i < 8; i++) {
        int gq = q0 + qb + 4 * i;
        if (gq < KS) g_attno[((size_t)(bt * KS + gq)) * CD + h * HD + dc] = acc[i];
    }
}

// --------------------------- elementwise helpers ----------------------------
__global__ void patchify_kernel(const float* __restrict__ x)
{
    int i = blockIdx.x * blockDim.x + threadIdx.x;
    if (i >= RT * CD) return;
    int k = i % CD; int r = i / CD;
    int n = r % NP; int bt = r / NP; int t = bt % TT; int b = bt / TT;
    int ci = k >> 8; int rem = k & 255; int py = rem >> 4; int px = rem & 15;
    int nh = n / 14, nw = n % 14;
    size_t src = ((((size_t)b * 3 + ci) * TT + t) * 224 + (nh * 16 + py)) * 224 + (nw * 16 + px);
    g_patches[i] = x[src];
}

__global__ void init_cls_kernel(const float* __restrict__ cls_token,
                                const float* __restrict__ pos_embed)
{
    int i = blockIdx.x * blockDim.x + threadIdx.x;
    if (i >= BATCH * CD) return;
    int b = i / CD, c = i % CD;
    g_xb[((size_t)b * SEQ) * CD + c] = cls_token[c] + pos_embed[c];
}

__global__ void init_patch_kernel(const float* __restrict__ pos_embed,
                                  const float* __restrict__ time_embed)
{
    int i = blockIdx.x * blockDim.x + threadIdx.x;
    if (i >= RT * CD) return;
    int c = i % CD; int r = i / CD;
    int n = r % NP; int bt = r / NP; int t = bt % TT; int b = bt / TT;
    g_xb[((size_t)b * SEQ + 1 + t * NP + n) * CD + c] =
        g_buf3[i] + pos_embed[(size_t)(1 + n) * CD + c] + time_embed[(size_t)t * CD + c];
}

__global__ void gather_time_kernel()
{
    int i = blockIdx.x * blockDim.x + threadIdx.x;
    if (i >= RT * CD) return;
    int c = i % CD; int r = i / CD;
    int t = r % TT; int bn = r / TT; int n = bn % NP; int b = bn / NP;
    g_buf1[i] = g_xb[((size_t)b * SEQ + 1 + t * NP + n) * CD + c];
}

__global__ void scatter_time_kernel()
{
    int i = blockIdx.x * blockDim.x + threadIdx.x;
    if (i >= RT * CD) return;
    int c = i % CD; int r = i / CD;
    int t = r % TT; int bn = r / TT; int n = bn % NP; int b = bn / NP;
    g_xb[((size_t)b * SEQ + 1 + t * NP + n) * CD + c] += g_buf1[i];
}

__global__ void gather_space_kernel()
{
    int i = blockIdx.x * blockDim.x + threadIdx.x;
    if (i >= RS * CD) return;
    int c = i % CD; int r = i / CD;
    int m = r % KS; int bt = r / KS; int t = bt % TT; int b = bt / TT;
    size_t src = (m == 0) ? ((size_t)b * SEQ) * CD + c
                          : ((size_t)b * SEQ + 1 + t * NP + (m - 1)) * CD + c;
    g_buf1[i] = g_xb[src];
}

__global__ void combine_space_kernel()
{
    int i = blockIdx.x * blockDim.x + threadIdx.x;
    if (i >= RT * CD) return;
    int c = i % CD; int r = i / CD;
    int n = r % NP; int bt = r / NP; int t = bt % TT; int b = bt / TT;
    g_xb[((size_t)b * SEQ + 1 + t * NP + n) * CD + c] +=
        g_buf3[((size_t)(bt * KS + 1 + n)) * CD + c];
}

__global__ void combine_cls_kernel()
{
    int i = blockIdx.x * blockDim.x + threadIdx.x;
    if (i >= BATCH * CD) return;
    int b = i / CD, c = i % CD;
    float s = 0.f;
    #pragma unroll
    for (int t = 0; t < TT; t++)
        s += g_buf3[((size_t)((b * TT + t) * KS)) * CD + c];
    g_xb[((size_t)b * SEQ) * CD + c] += s * (1.f / TT);
}

__global__ void add_residual_kernel()
{
    int i = blockIdx.x * blockDim.x + threadIdx.x;
    if (i >= RX * CD) return;
    g_xb[i] += g_buf3[i];
}

// ------------------------------- head ---------------------------------------
__global__ void __launch_bounds__(256) head_kernel(
    const float* __restrict__ hw, const float* __restrict__ hb,
    float* __restrict__ out)
{
    const int warp = threadIdx.x >> 5, lane = threadIdx.x & 31;
    const int o = blockIdx.x * 8 + warp;
    if (o >= BATCH * 1000) return;
    const int b = o / 1000, j = o % 1000;
    const float* xr = g_buf2 + (size_t)b * SEQ * CD;   // final-LN output, cls row
    const float* wr = hw + (size_t)j * CD;
    float s = 0.f;
    for (int k = lane; k < CD; k += 32) s += xr[k] * wr[k];
    #pragma unroll
    for (int off = 16; off; off >>= 1) s += __shfl_down_sync(0xffffffffu, s, off);
    if (lane == 0) out[o] = s + hb[j];
}

// ------------------------------ launcher ------------------------------------
static inline int cdiv(int a, int b) { return (a + b - 1) / b; }

static void gemm(const float* A, const float* W, const float* B, float* C,
                 int M, int N, int K, int act)
{
    dim3 gr(cdiv(N, 128), cdiv(M, 128));
    sgemm_kernel<<<gr, 256>>>(A, W, B, C, M, N, K, act);
}

extern "C" void kernel_launch(void* const* d_in, const int* in_sizes, int n_in,
                              void* d_out, int out_size)
{
    const float* x          = (const float*)d_in[0];
    const float* conv_w     = (const float*)d_in[1];
    const float* conv_b     = (const float*)d_in[2];
    const float* cls_token  = (const float*)d_in[3];
    const float* pos_embed  = (const float*)d_in[4];
    const float* time_embed = (const float*)d_in[5];
    const float* tn_w   = (const float*)d_in[6];
    const float* tn_b   = (const float*)d_in[7];
    const float* tqkv_w = (const float*)d_in[8];
    const float* tqkv_b = (const float*)d_in[9];
    const float* tproj_w= (const float*)d_in[10];
    const float* tproj_b= (const float*)d_in[11];
    const float* tfc_w  = (const float*)d_in[12];
    const float* tfc_b  = (const float*)d_in[13];
    const float* n1_w   = (const float*)d_in[14];
    const float* n1_b   = (const float*)d_in[15];
    const float* sqkv_w = (const float*)d_in[16];
    const float* sqkv_b = (const float*)d_in[17];
    const float* sproj_w= (const float*)d_in[18];
    const float* sproj_b= (const float*)d_in[19];
    const float* n2_w   = (const float*)d_in[20];
    const float* n2_b   = (const float*)d_in[21];
    const float* fc1_w  = (const float*)d_in[22];
    const float* fc1_b  = (const float*)d_in[23];
    const float* fc2_w  = (const float*)d_in[24];
    const float* fc2_b  = (const float*)d_in[25];
    const float* norm_w = (const float*)d_in[26];
    const float* norm_b = (const float*)d_in[27];
    const float* head_w = (const float*)d_in[28];
    const float* head_b = (const float*)d_in[29];

    float *xb, *patches, *buf1, *buf2, *buf3, *attno, *qkv, *fc1;
    cudaGetSymbolAddress((void**)&xb,      g_xb);
    cudaGetSymbolAddress((void**)&patches, g_patches);
    cudaGetSymbolAddress((void**)&buf1,    g_buf1);
    cudaGetSymbolAddress((void**)&buf2,    g_buf2);
    cudaGetSymbolAddress((void**)&buf3,    g_buf3);
    cudaGetSymbolAddress((void**)&attno,   g_attno);
    cudaGetSymbolAddress((void**)&qkv,     g_qkv);
    cudaGetSymbolAddress((void**)&fc1,     g_fc1);

    const int EB = 256;

    // ---- patch embedding + pos/time embed + cls init ----
    patchify_kernel<<<cdiv(RT * CD, EB), EB>>>(x);
    gemm(patches, conv_w, conv_b, buf3, RT, CD, CD, 0);
    init_cls_kernel<<<cdiv(BATCH * CD, EB), EB>>>(cls_token, pos_embed);
    init_patch_kernel<<<cdiv(RT * CD, EB), EB>>>(pos_embed, time_embed);

    // ---- transformer blocks ----
    for (int l = 0; l < DEPTH; l++) {
        // ===== time attention =====
        gather_time_kernel<<<cdiv(RT * CD, EB), EB>>>();
        ln_kernel<<<RT, 256>>>(buf1, buf2, tn_w + (size_t)l * CD, tn_b + (size_t)l * CD);
        gemm(buf2, tqkv_w + (size_t)l * 3 * CD * CD, tqkv_b + (size_t)l * 3 * CD,
             qkv, RT, 3 * CD, CD, 0);
        time_attn_kernel<<<(RT / TT) * NH, 64>>>();
        gemm(attno, tproj_w + (size_t)l * CD * CD, tproj_b + (size_t)l * CD,
             buf3, RT, CD, CD, 0);
        gemm(buf3, tfc_w + (size_t)l * CD * CD, tfc_b + (size_t)l * CD,
             buf1, RT, CD, CD, 0);
        scatter_time_kernel<<<cdiv(RT * CD, EB), EB>>>();

        // ===== space attention =====
        gather_space_kernel<<<cdiv(RS * CD, EB), EB>>>();
        ln_kernel<<<RS, 256>>>(buf1, buf2, n1_w + (size_t)l * CD, n1_b + (size_t)l * CD);
        gemm(buf2, sqkv_w + (size_t)l * 3 * CD * CD, sqkv_b + (size_t)l * 3 * CD,
             qkv, RS, 3 * CD, CD, 0);
        {
            dim3 gr(GROUPS, cdiv(KS, 32), cdiv(KS, 64));
            space_scores_kernel<<<gr, 256>>>();
        }
        softmax197_kernel<<<GROUPS * KS, 32>>>();
        {
            dim3 gr(GROUPS, cdiv(KS, 32));
            space_pv_kernel<<<gr, 256>>>();
        }
        gemm(attno, sproj_w + (size_t)l * CD * CD, sproj_b + (size_t)l * CD,
             buf3, RS, CD, CD, 0);
        combine_space_kernel<<<cdiv(RT * CD, EB), EB>>>();
        combine_cls_kernel<<<cdiv(BATCH * CD, EB), EB>>>();

        // ===== MLP =====
        ln_kernel<<<RX, 256>>>(xb, buf2, n2_w + (size_t)l * CD, n2_b + (size_t)l * CD);
        gemm(buf2, fc1_w + (size_t)l * 4 * CD * CD, fc1_b + (size_t)l * 4 * CD,
             fc1, RX, 4 * CD, CD, 1);
        gemm(fc1, fc2_w + (size_t)l * CD * 4 * CD, fc2_b + (size_t)l * CD,
             buf3, RX, CD, 4 * CD, 0);
        add_residual_kernel<<<cdiv(RX * CD, EB), EB>>>();
    }

    // ---- final norm + head ----
    ln_kernel<<<RX, 256>>>(xb, buf2, norm_w, norm_b);
    head_kernel<<<cdiv(BATCH * 1000, 8), 256>>>(head_w, head_b, (float*)d_out);
}

// round 5
// speedup vs baseline: 1.5419x; 1.5419x over previous
#include <cuda_runtime.h>
#include <math.h>
#include <stdint.h>

// ---------------------------------------------------------------------------
// TimeSformer forward. B=2, T=8, N=196, C=768, H=12, hd=64, depth=12.
// GEMMs: 3xTF32 tensor-core (near-fp32 accuracy). Rest: fp32 SIMT.
// ---------------------------------------------------------------------------

constexpr int BATCH = 2;
constexpr int TT    = 8;
constexpr int NP    = 196;
constexpr int CD    = 768;
constexpr int NH    = 12;
constexpr int HD    = 64;
constexpr int SEQ   = 1 + TT * NP;          // 1569
constexpr int RT    = BATCH * TT * NP;      // 3136 rows (time-attn view)
constexpr int KS    = NP + 1;               // 197
constexpr int RS    = BATCH * TT * KS;      // 3152 rows (space-attn view)
constexpr int RX    = BATCH * SEQ;          // 3138 rows (full stream)
constexpr int GROUPS= BATCH * TT * NH;      // 192 attention groups
constexpr int DEPTH = 12;

// -------------------------- scratch (device globals) -----------------------
__device__ float g_xb     [(size_t)BATCH * SEQ * CD];
__device__ float g_patches[(size_t)RT * CD];
__device__ float g_buf1   [(size_t)RS * CD];
__device__ float g_buf2   [(size_t)RS * CD];
__device__ float g_buf3   [(size_t)RS * CD];
__device__ float g_attno  [(size_t)RS * CD];
__device__ float g_qkv    [(size_t)RS * 3 * CD];
__device__ float g_scores [(size_t)GROUPS * KS * KS];
__device__ float g_fc1    [(size_t)RX * 4 * CD];

// ------------------------- 3xTF32 tensor-core GEMM --------------------------
// C[m,n] = sum_k A[m,k]*W[n,k] + bias[n].  A: MxK rm, W: NxK rm, C: MxN rm.
// N, K multiples of 128/16; M guarded. act==1 -> exact GELU epilogue.

__device__ __forceinline__ void split_tf32(float f, uint32_t& hi, uint32_t& lo)
{
    asm("cvt.rna.tf32.f32 %0, %1;" : "=r"(hi) : "f"(f));
    float r = f - __uint_as_float(hi);
    asm("cvt.rna.tf32.f32 %0, %1;" : "=r"(lo) : "f"(r));
}

__device__ __forceinline__ void mma_tf32(float* c, const uint32_t* a,
                                         uint32_t b0, uint32_t b1)
{
    asm volatile(
        "mma.sync.aligned.m16n8k8.row.col.f32.tf32.tf32.f32 "
        "{%0,%1,%2,%3}, {%4,%5,%6,%7}, {%8,%9}, {%0,%1,%2,%3};"
        : "+f"(c[0]), "+f"(c[1]), "+f"(c[2]), "+f"(c[3])
        : "r"(a[0]), "r"(a[1]), "r"(a[2]), "r"(a[3]), "r"(b0), "r"(b1));
}

__device__ __forceinline__ void cpa16(uint32_t dst, const void* src, int srcsz)
{
    asm volatile("cp.async.ca.shared.global [%0], [%1], 16, %2;"
                 :: "r"(dst), "l"(src), "r"(srcsz));
}

constexpr int LDK = 20;   // 16 + 4 pad: conflict-free fragment loads

__global__ void __launch_bounds__(256, 2) tc_gemm_kernel(
    const float* __restrict__ A, const float* __restrict__ W,
    const float* __restrict__ bias, float* __restrict__ C,
    int M, int N, int K, int act)
{
    __shared__ float As[2][128][LDK];
    __shared__ float Bs[2][128][LDK];

    const int tid  = threadIdx.x;
    const int wid  = tid >> 5;
    const int lane = tid & 31;
    const int wm   = wid >> 2;          // 0..1  (64-row warp tile)
    const int wn   = wid & 3;           // 0..3  (32-col warp tile)
    const int g    = lane >> 2;         // 0..7
    const int q    = lane & 3;          // 0..3
    const int row0 = blockIdx.y * 128;
    const int col0 = blockIdx.x * 128;

    float acc[4][4][4];
    #pragma unroll
    for (int i = 0; i < 4; i++)
        #pragma unroll
        for (int j = 0; j < 4; j++)
            #pragma unroll
            for (int v = 0; v < 4; v++) acc[i][j][v] = 0.f;

    // loader mapping: 2 float4 per tile per thread per operand
    const int ldr = tid >> 2;           // 0..63
    const int lfc = (tid & 3) * 4;      // float offset within k16
    const uint32_t asb = (uint32_t)__cvta_generic_to_shared(&As[0][0][0]);
    const uint32_t bsb = (uint32_t)__cvta_generic_to_shared(&Bs[0][0][0]);

    const int T = K / 16;

    auto prefetch = [&](int t, int s) {
        const int k0 = t * 16 + lfc;
        #pragma unroll
        for (int h = 0; h < 2; h++) {
            int r = ldr + 64 * h;
            int gr = row0 + r;
            int ok = (gr < M) ? 16 : 0;
            int cr = (gr < M) ? gr : (M - 1);
            cpa16(asb + (((s * 128 + r) * LDK + lfc) << 2),
                  A + (size_t)cr * K + k0, ok);
            cpa16(bsb + (((s * 128 + r) * LDK + lfc) << 2),
                  W + (size_t)(col0 + r) * K + k0, 16);
        }
        asm volatile("cp.async.commit_group;" ::: "memory");
    };

    prefetch(0, 0);

    for (int t = 0; t < T; t++) {
        const int s = t & 1;
        asm volatile("cp.async.wait_group 0;" ::: "memory");
        __syncthreads();
        if (t + 1 < T) prefetch(t + 1, (t + 1) & 1);

        #pragma unroll
        for (int ks = 0; ks < 16; ks += 8) {
            uint32_t ahi[4][4], alo[4][4];
            #pragma unroll
            for (int mt = 0; mt < 4; mt++) {
                int r = wm * 64 + mt * 16 + g;
                float f0 = As[s][r][ks + q];
                float f1 = As[s][r + 8][ks + q];
                float f2 = As[s][r][ks + q + 4];
                float f3 = As[s][r + 8][ks + q + 4];
                split_tf32(f0, ahi[mt][0], alo[mt][0]);
                split_tf32(f1, ahi[mt][1], alo[mt][1]);
                split_tf32(f2, ahi[mt][2], alo[mt][2]);
                split_tf32(f3, ahi[mt][3], alo[mt][3]);
            }
            #pragma unroll
            for (int nt = 0; nt < 4; nt++) {
                int c = wn * 32 + nt * 8 + g;
                float g0 = Bs[s][c][ks + q];
                float g1 = Bs[s][c][ks + q + 4];
                uint32_t bh0, bl0, bh1, bl1;
                split_tf32(g0, bh0, bl0);
                split_tf32(g1, bh1, bl1);
                #pragma unroll
                for (int mt = 0; mt < 4; mt++) {
                    mma_tf32(acc[mt][nt], alo[mt], bh0, bh1);  // lo*hi
                    mma_tf32(acc[mt][nt], ahi[mt], bl0, bl1);  // hi*lo
                    mma_tf32(acc[mt][nt], ahi[mt], bh0, bh1);  // hi*hi
                }
            }
        }
        __syncthreads();
    }

    // epilogue
    #pragma unroll
    for (int mt = 0; mt < 4; mt++) {
        int r0 = row0 + wm * 64 + mt * 16 + g;
        #pragma unroll
        for (int nt = 0; nt < 4; nt++) {
            int cc = col0 + wn * 32 + nt * 8 + 2 * q;
            float b0 = bias[cc], b1 = bias[cc + 1];
            if (r0 < M) {
                float v0 = acc[mt][nt][0] + b0;
                float v1 = acc[mt][nt][1] + b1;
                if (act) { v0 = v0 * normcdff(v0); v1 = v1 * normcdff(v1); }
                *(float2*)&C[(size_t)r0 * N + cc] = make_float2(v0, v1);
            }
            if (r0 + 8 < M) {
                float v2 = acc[mt][nt][2] + b0;
                float v3 = acc[mt][nt][3] + b1;
                if (act) { v2 = v2 * normcdff(v2); v3 = v3 * normcdff(v3); }
                *(float2*)&C[(size_t)(r0 + 8) * N + cc] = make_float2(v2, v3);
            }
        }
    }
}

// ------------------------------ LayerNorm -----------------------------------
__device__ __forceinline__ float blk_sum(float v, float* sm)
{
    const int lane = threadIdx.x & 31, w = threadIdx.x >> 5;
    #pragma unroll
    for (int o = 16; o; o >>= 1) v += __shfl_xor_sync(0xffffffffu, v, o);
    if (lane == 0) sm[w] = v;
    __syncthreads();
    if (threadIdx.x == 0) {
        float t = 0.f;
        #pragma unroll
        for (int i = 0; i < 8; i++) t += sm[i];
        sm[8] = t;
    }
    __syncthreads();
    float t = sm[8];
    __syncthreads();
    return t;
}

__global__ void __launch_bounds__(256) ln_kernel(
    const float* __restrict__ in, float* __restrict__ out,
    const float* __restrict__ w, const float* __restrict__ b)
{
    __shared__ float sm[9];
    const size_t r = blockIdx.x;
    const float* x = in + r * CD;
    const int t = threadIdx.x;
    float v0 = x[t], v1 = x[t + 256], v2 = x[t + 512];
    float tot = blk_sum(v0 + v1 + v2, sm);
    float mean = tot * (1.0f / CD);
    float d0 = v0 - mean, d1 = v1 - mean, d2 = v2 - mean;
    float tot2 = blk_sum(d0 * d0 + d1 * d1 + d2 * d2, sm);
    float inv = rsqrtf(tot2 * (1.0f / CD) + 1e-6f);
    float* o = out + r * CD;
    o[t]       = d0 * inv * w[t]       + b[t];
    o[t + 256] = d1 * inv * w[t + 256] + b[t + 256];
    o[t + 512] = d2 * inv * w[t + 512] + b[t + 512];
}

// ------------------------- Time attention (seq=8) ---------------------------
__global__ void __launch_bounds__(64) time_attn_kernel()
{
    const int g = blockIdx.x;
    const int h = g % NH;
    const int bn = g / NH;
    const int lane = threadIdx.x;
    __shared__ float Q[TT][HD + 1], Kk[TT][HD + 1], V[TT][HD + 1];
    __shared__ float P[TT][TT + 1];
    #pragma unroll
    for (int t = 0; t < TT; t++) {
        size_t base = ((size_t)(bn * TT + t)) * (3 * CD) + h * HD + lane;
        Q[t][lane]  = g_qkv[base];
        Kk[t][lane] = g_qkv[base + CD];
        V[t][lane]  = g_qkv[base + 2 * CD];
    }
    __syncthreads();
    const int tq = lane >> 3, tk = lane & 7;
    float s = 0.f;
    #pragma unroll
    for (int d = 0; d < HD; d++) s += Q[tq][d] * Kk[tk][d];
    P[tq][tk] = s * 0.125f;
    __syncthreads();
    if (lane < TT) {
        float m = -1e30f;
        #pragma unroll
        for (int k = 0; k < TT; k++) m = fmaxf(m, P[lane][k]);
        float sum = 0.f;
        #pragma unroll
        for (int k = 0; k < TT; k++) { float e = expf(P[lane][k] - m); P[lane][k] = e; sum += e; }
        float inv = 1.f / sum;
        #pragma unroll
        for (int k = 0; k < TT; k++) P[lane][k] *= inv;
    }
    __syncthreads();
    #pragma unroll
    for (int t = 0; t < TT; t++) {
        float a = 0.f;
        #pragma unroll
        for (int k = 0; k < TT; k++) a += P[t][k] * V[k][lane];
        g_attno[((size_t)(bn * TT + t)) * CD + h * HD + lane] = a;
    }
}

// ------------------------- Space attention (seq=197) ------------------------
__global__ void __launch_bounds__(256) space_scores_kernel()
{
    const int g = blockIdx.x;
    const int h = g % NH, bt = g / NH;
    const int q0 = blockIdx.y * 32, k0 = blockIdx.z * 64;
    __shared__ float Qs[32][HD + 1];
    __shared__ float Ksm[64][HD + 1];
    const int tid = threadIdx.x;
    for (int i = tid; i < 32 * 64; i += 256) {
        int r = i >> 6, d = i & 63; int gq = q0 + r;
        Qs[r][d] = (gq < KS) ? g_qkv[((size_t)(bt * KS + gq)) * (3 * CD) + h * HD + d] : 0.f;
    }
    for (int i = tid; i < 64 * 64; i += 256) {
        int r = i >> 6, d = i & 63; int gk = k0 + r;
        Ksm[r][d] = (gk < KS) ? g_qkv[((size_t)(bt * KS + gk)) * (3 * CD) + CD + h * HD + d] : 0.f;
    }
    __syncthreads();
    const int kc = tid & 63, qb = tid >> 6;
    float s[8];
    #pragma unroll
    for (int i = 0; i < 8; i++) s[i] = 0.f;
    #pragma unroll
    for (int d = 0; d < HD; d++) {
        float kv = Ksm[kc][d];
        #pragma unroll
        for (int i = 0; i < 8; i++) s[i] = fmaf(Qs[qb + 4 * i][d], kv, s[i]);
    }
    const int gk = k0 + kc;
    if (gk < KS) {
        #pragma unroll
        for (int i = 0; i < 8; i++) {
            int gq = q0 + qb + 4 * i;
            if (gq < KS) g_scores[((size_t)g * KS + gq) * KS + gk] = s[i] * 0.125f;
        }
    }
}

__global__ void __launch_bounds__(32) softmax197_kernel()
{
    const size_t row = blockIdx.x;
    float* p = g_scores + row * KS;
    const int lane = threadIdx.x;
    float vals[7];
    float m = -1e30f;
    #pragma unroll
    for (int i = 0; i < 7; i++) {
        int j = lane + 32 * i;
        vals[i] = (j < KS) ? p[j] : -1e30f;
        m = fmaxf(m, vals[i]);
    }
    #pragma unroll
    for (int o = 16; o; o >>= 1) m = fmaxf(m, __shfl_xor_sync(0xffffffffu, m, o));
    float s = 0.f;
    #pragma unroll
    for (int i = 0; i < 7; i++) {
        int j = lane + 32 * i;
        if (j < KS) { vals[i] = expf(vals[i] - m); s += vals[i]; }
    }
    #pragma unroll
    for (int o = 16; o; o >>= 1) s += __shfl_xor_sync(0xffffffffu, s, o);
    float inv = 1.f / s;
    #pragma unroll
    for (int i = 0; i < 7; i++) {
        int j = lane + 32 * i;
        if (j < KS) p[j] = vals[i] * inv;
    }
}

__global__ void __launch_bounds__(256) space_pv_kernel()
{
    const int g = blockIdx.x;
    const int h = g % NH, bt = g / NH;
    const int q0 = blockIdx.y * 32;
    __shared__ float Ps[32][33];
    __shared__ float Vs[32][HD + 1];
    const int tid = threadIdx.x;
    const int dc = tid & 63, qb = tid >> 6;
    float acc[8];
    #pragma unroll
    for (int i = 0; i < 8; i++) acc[i] = 0.f;
    for (int c0 = 0; c0 < KS; c0 += 32) {
        for (int i = tid; i < 32 * 32; i += 256) {
            int r = i >> 5, c = i & 31; int gq = q0 + r, gk = c0 + c;
            Ps[r][c] = (gq < KS && gk < KS) ? g_scores[((size_t)g * KS + gq) * KS + gk] : 0.f;
        }
        for (int i = tid; i < 32 * 64; i += 256) {
            int r = i >> 6, d = i & 63; int gk = c0 + r;
            Vs[r][d] = (gk < KS) ? g_qkv[((size_t)(bt * KS + gk)) * (3 * CD) + 2 * CD + h * HD + d] : 0.f;
        }
        __syncthreads();
        #pragma unroll
        for (int kk = 0; kk < 32; kk++) {
            float vv = Vs[kk][dc];
            #pragma unroll
            for (int i = 0; i < 8; i++) acc[i] = fmaf(Ps[qb + 4 * i][kk], vv, acc[i]);
        }
        __syncthreads();
    }
    #pragma unroll
    for (int i = 0; i < 8; i++) {
        int gq = q0 + qb + 4 * i;
        if (gq < KS) g_attno[((size_t)(bt * KS + gq)) * CD + h * HD + dc] = acc[i];
    }
}

// --------------------------- elementwise helpers ----------------------------
__global__ void patchify_kernel(const float* __restrict__ x)
{
    int i = blockIdx.x * blockDim.x + threadIdx.x;
    if (i >= RT * CD) return;
    int k = i % CD; int r = i / CD;
    int n = r % NP; int bt = r / NP; int t = bt % TT; int b = bt / TT;
    int ci = k >> 8; int rem = k & 255; int py = rem >> 4; int px = rem & 15;
    int nh = n / 14, nw = n % 14;
    size_t src = ((((size_t)b * 3 + ci) * TT + t) * 224 + (nh * 16 + py)) * 224 + (nw * 16 + px);
    g_patches[i] = x[src];
}

__global__ void init_cls_kernel(const float* __restrict__ cls_token,
                                const float* __restrict__ pos_embed)
{
    int i = blockIdx.x * blockDim.x + threadIdx.x;
    if (i >= BATCH * CD) return;
    int b = i / CD, c = i % CD;
    g_xb[((size_t)b * SEQ) * CD + c] = cls_token[c] + pos_embed[c];
}

__global__ void init_patch_kernel(const float* __restrict__ pos_embed,
                                  const float* __restrict__ time_embed)
{
    int i = blockIdx.x * blockDim.x + threadIdx.x;
    if (i >= RT * CD) return;
    int c = i % CD; int r = i / CD;
    int n = r % NP; int bt = r / NP; int t = bt % TT; int b = bt / TT;
    g_xb[((size_t)b * SEQ + 1 + t * NP + n) * CD + c] =
        g_buf3[i] + pos_embed[(size_t)(1 + n) * CD + c] + time_embed[(size_t)t * CD + c];
}

__global__ void gather_time_kernel()
{
    int i = blockIdx.x * blockDim.x + threadIdx.x;
    if (i >= RT * CD) return;
    int c = i % CD; int r = i / CD;
    int t = r % TT; int bn = r / TT; int n = bn % NP; int b = bn / NP;
    g_buf1[i] = g_xb[((size_t)b * SEQ + 1 + t * NP + n) * CD + c];
}

__global__ void scatter_time_kernel()
{
    int i = blockIdx.x * blockDim.x + threadIdx.x;
    if (i >= RT * CD) return;
    int c = i % CD; int r = i / CD;
    int t = r % TT; int bn = r / TT; int n = bn % NP; int b = bn / NP;
    g_xb[((size_t)b * SEQ + 1 + t * NP + n) * CD + c] += g_buf1[i];
}

__global__ void gather_space_kernel()
{
    int i = blockIdx.x * blockDim.x + threadIdx.x;
    if (i >= RS * CD) return;
    int c = i % CD; int r = i / CD;
    int m = r % KS; int bt = r / KS; int t = bt % TT; int b = bt / TT;
    size_t src = (m == 0) ? ((size_t)b * SEQ) * CD + c
                          : ((size_t)b * SEQ + 1 + t * NP + (m - 1)) * CD + c;
    g_buf1[i] = g_xb[src];
}

__global__ void combine_space_kernel()
{
    int i = blockIdx.x * blockDim.x + threadIdx.x;
    if (i >= RT * CD) return;
    int c = i % CD; int r = i / CD;
    int n = r % NP; int bt = r / NP; int t = bt % TT; int b = bt / TT;
    g_xb[((size_t)b * SEQ + 1 + t * NP + n) * CD + c] +=
        g_buf3[((size_t)(bt * KS + 1 + n)) * CD + c];
}

__global__ void combine_cls_kernel()
{
    int i = blockIdx.x * blockDim.x + threadIdx.x;
    if (i >= BATCH * CD) return;
    int b = i / CD, c = i % CD;
    float s = 0.f;
    #pragma unroll
    for (int t = 0; t < TT; t++)
        s += g_buf3[((size_t)((b * TT + t) * KS)) * CD + c];
    g_xb[((size_t)b * SEQ) * CD + c] += s * (1.f / TT);
}

__global__ void add_residual_kernel()
{
    int i = blockIdx.x * blockDim.x + threadIdx.x;
    if (i >= RX * CD) return;
    g_xb[i] += g_buf3[i];
}

// ------------------------------- head ---------------------------------------
__global__ void __launch_bounds__(256) head_kernel(
    const float* __restrict__ hw, const float* __restrict__ hb,
    float* __restrict__ out)
{
    const int warp = threadIdx.x >> 5, lane = threadIdx.x & 31;
    const int o = blockIdx.x * 8 + warp;
    if (o >= BATCH * 1000) return;
    const int b = o / 1000, j = o % 1000;
    const float* xr = g_buf2 + (size_t)b * SEQ * CD;
    const float* wr = hw + (size_t)j * CD;
    float s = 0.f;
    for (int k = lane; k < CD; k += 32) s += xr[k] * wr[k];
    #pragma unroll
    for (int off = 16; off; off >>= 1) s += __shfl_down_sync(0xffffffffu, s, off);
    if (lane == 0) out[o] = s + hb[j];
}

// ------------------------------ launcher ------------------------------------
static inline int cdiv(int a, int b) { return (a + b - 1) / b; }

static void gemm(const float* A, const float* W, const float* B, float* C,
                 int M, int N, int K, int act)
{
    dim3 gr(N / 128, cdiv(M, 128));
    tc_gemm_kernel<<<gr, 256>>>(A, W, B, C, M, N, K, act);
}

extern "C" void kernel_launch(void* const* d_in, const int* in_sizes, int n_in,
                              void* d_out, int out_size)
{
    const float* x          = (const float*)d_in[0];
    const float* conv_w     = (const float*)d_in[1];
    const float* conv_b     = (const float*)d_in[2];
    const float* cls_token  = (const float*)d_in[3];
    const float* pos_embed  = (const float*)d_in[4];
    const float* time_embed = (const float*)d_in[5];
    const float* tn_w   = (const float*)d_in[6];
    const float* tn_b   = (const float*)d_in[7];
    const float* tqkv_w = (const float*)d_in[8];
    const float* tqkv_b = (const float*)d_in[9];
    const float* tproj_w= (const float*)d_in[10];
    const float* tproj_b= (const float*)d_in[11];
    const float* tfc_w  = (const float*)d_in[12];
    const float* tfc_b  = (const float*)d_in[13];
    const float* n1_w   = (const float*)d_in[14];
    const float* n1_b   = (const float*)d_in[15];
    const float* sqkv_w = (const float*)d_in[16];
    const float* sqkv_b = (const float*)d_in[17];
    const float* sproj_w= (const float*)d_in[18];
    const float* sproj_b= (const float*)d_in[19];
    const float* n2_w   = (const float*)d_in[20];
    const float* n2_b   = (const float*)d_in[21];
    const float* fc1_w  = (const float*)d_in[22];
    const float* fc1_b  = (const float*)d_in[23];
    const float* fc2_w  = (const float*)d_in[24];
    const float* fc2_b  = (const float*)d_in[25];
    const float* norm_w = (const float*)d_in[26];
    const float* norm_b = (const float*)d_in[27];
    const float* head_w = (const float*)d_in[28];
    const float* head_b = (const float*)d_in[29];

    float *xb, *patches, *buf1, *buf2, *buf3, *attno, *qkv, *fc1;
    cudaGetSymbolAddress((void**)&xb,      g_xb);
    cudaGetSymbolAddress((void**)&patches, g_patches);
    cudaGetSymbolAddress((void**)&buf1,    g_buf1);
    cudaGetSymbolAddress((void**)&buf2,    g_buf2);
    cudaGetSymbolAddress((void**)&buf3,    g_buf3);
    cudaGetSymbolAddress((void**)&attno,   g_attno);
    cudaGetSymbolAddress((void**)&qkv,     g_qkv);
    cudaGetSymbolAddress((void**)&fc1,     g_fc1);

    const int EB = 256;

    // ---- patch embedding + pos/time embed + cls init ----
    patchify_kernel<<<cdiv(RT * CD, EB), EB>>>(x);
    gemm(patches, conv_w, conv_b, buf3, RT, CD, CD, 0);
    init_cls_kernel<<<cdiv(BATCH * CD, EB), EB>>>(cls_token, pos_embed);
    init_patch_kernel<<<cdiv(RT * CD, EB), EB>>>(pos_embed, time_embed);

    // ---- transformer blocks ----
    for (int l = 0; l < DEPTH; l++) {
        // ===== time attention =====
        gather_time_kernel<<<cdiv(RT * CD, EB), EB>>>();
        ln_kernel<<<RT, 256>>>(buf1, buf2, tn_w + (size_t)l * CD, tn_b + (size_t)l * CD);
        gemm(buf2, tqkv_w + (size_t)l * 3 * CD * CD, tqkv_b + (size_t)l * 3 * CD,
             qkv, RT, 3 * CD, CD, 0);
        time_attn_kernel<<<(RT / TT) * NH, 64>>>();
        gemm(attno, tproj_w + (size_t)l * CD * CD, tproj_b + (size_t)l * CD,
             buf3, RT, CD, CD, 0);
        gemm(buf3, tfc_w + (size_t)l * CD * CD, tfc_b + (size_t)l * CD,
             buf1, RT, CD, CD, 0);
        scatter_time_kernel<<<cdiv(RT * CD, EB), EB>>>();

        // ===== space attention =====
        gather_space_kernel<<<cdiv(RS * CD, EB), EB>>>();
        ln_kernel<<<RS, 256>>>(buf1, buf2, n1_w + (size_t)l * CD, n1_b + (size_t)l * CD);
        gemm(buf2, sqkv_w + (size_t)l * 3 * CD * CD, sqkv_b + (size_t)l * 3 * CD,
             qkv, RS, 3 * CD, CD, 0);
        {
            dim3 gr(GROUPS, cdiv(KS, 32), cdiv(KS, 64));
            space_scores_kernel<<<gr, 256>>>();
        }
        softmax197_kernel<<<GROUPS * KS, 32>>>();
        {
            dim3 gr(GROUPS, cdiv(KS, 32));
            space_pv_kernel<<<gr, 256>>>();
        }
        gemm(attno, sproj_w + (size_t)l * CD * CD, sproj_b + (size_t)l * CD,
             buf3, RS, CD, CD, 0);
        combine_space_kernel<<<cdiv(RT * CD, EB), EB>>>();
        combine_cls_kernel<<<cdiv(BATCH * CD, EB), EB>>>();

        // ===== MLP =====
        ln_kernel<<<RX, 256>>>(xb, buf2, n2_w + (size_t)l * CD, n2_b + (size_t)l * CD);
        gemm(buf2, fc1_w + (size_t)l * 4 * CD * CD, fc1_b + (size_t)l * 4 * CD,
             fc1, RX, 4 * CD, CD, 1);
        gemm(fc1, fc2_w + (size_t)l * CD * 4 * CD, fc2_b + (size_t)l * CD,
             buf3, RX, CD, 4 * CD, 0);
        add_residual_kernel<<<cdiv(RX * CD, EB), EB>>>();
    }

    // ---- final norm + head ----
    ln_kernel<<<RX, 256>>>(xb, buf2, norm_w, norm_b);
    head_kernel<<<cdiv(BATCH * 1000, 8), 256>>>(head_w, head_b, (float*)d_out);
}

// round 6
// speedup vs baseline: 2.2476x; 1.4576x over previous
#include <cuda_runtime.h>
#include <cuda_bf16.h>
#include <math.h>
#include <stdint.h>

// ---------------------------------------------------------------------------
// TimeSformer forward. B=2, T=8, N=196, C=768, H=12, hd=64, depth=12.
// GEMMs: bf16x3 tensor-core (hi/lo split emulation, near-fp32 accuracy).
// All GEMM inputs are pre-split into bf16 hi/lo by producers.
// ---------------------------------------------------------------------------

constexpr int BATCH = 2;
constexpr int TT    = 8;
constexpr int NP    = 196;
constexpr int CD    = 768;
constexpr int NH    = 12;
constexpr int HD    = 64;
constexpr int SEQ   = 1 + TT * NP;          // 1569
constexpr int RT    = BATCH * TT * NP;      // 3136
constexpr int KS    = NP + 1;               // 197
constexpr int RS    = BATCH * TT * KS;      // 3152
constexpr int RX    = BATCH * SEQ;          // 3138
constexpr int GROUPS= BATCH * TT * NH;      // 192
constexpr int DEPTH = 12;

// -------------------------- scratch (device globals) -----------------------
__device__ float g_xb     [(size_t)BATCH * SEQ * CD];
__device__ float g_buf1   [(size_t)RS * CD];
__device__ float g_buf2   [(size_t)RS * CD];
__device__ float g_buf3   [(size_t)RS * CD];
__device__ float g_qkv    [(size_t)RS * 3 * CD];
__device__ float g_scores [(size_t)GROUPS * KS * KS];

// hi/lo split activation buffers
__device__ __nv_bfloat16 g_ln_hi[(size_t)RS * CD];
__device__ __nv_bfloat16 g_ln_lo[(size_t)RS * CD];
__device__ __nv_bfloat16 g_at_hi[(size_t)RS * CD];
__device__ __nv_bfloat16 g_at_lo[(size_t)RS * CD];
__device__ __nv_bfloat16 g_f1_hi[(size_t)RX * 4 * CD];
__device__ __nv_bfloat16 g_f1_lo[(size_t)RX * 4 * CD];
__device__ __nv_bfloat16 g_pa_hi[(size_t)RT * CD];
__device__ __nv_bfloat16 g_pa_lo[(size_t)RT * CD];

// weight split buffers
constexpr size_t SZ_TQKV = (size_t)DEPTH * 3 * CD * CD;
constexpr size_t SZ_CC   = (size_t)DEPTH * CD * CD;
constexpr size_t SZ_FC   = (size_t)DEPTH * 4 * CD * CD;
constexpr size_t W_TQKV  = 0;
constexpr size_t W_TPROJ = W_TQKV + SZ_TQKV;
constexpr size_t W_TFC   = W_TPROJ + SZ_CC;
constexpr size_t W_SQKV  = W_TFC + SZ_CC;
constexpr size_t W_SPROJ = W_SQKV + SZ_TQKV;
constexpr size_t W_FC1   = W_SPROJ + SZ_CC;
constexpr size_t W_FC2   = W_FC1 + SZ_FC;
constexpr size_t W_CONV  = W_FC2 + SZ_FC;
constexpr size_t W_TOTAL = W_CONV + (size_t)CD * CD;

__device__ __nv_bfloat16 g_w_hi[W_TOTAL];
__device__ __nv_bfloat16 g_w_lo[W_TOTAL];

// ------------------------------ split helper --------------------------------
__device__ __forceinline__ void split2(float x, __nv_bfloat16& h, __nv_bfloat16& l)
{
    h = __float2bfloat16(x);
    l = __float2bfloat16(x - __bfloat162float(h));
}

// ------------------------- weight split kernel -------------------------------
__global__ void __launch_bounds__(256) wsplit_kernel(
    const float4* __restrict__ src, __nv_bfloat162* __restrict__ hi,
    __nv_bfloat162* __restrict__ lo, long n4)
{
    long i = blockIdx.x * (long)blockDim.x + threadIdx.x;
    if (i >= n4) return;
    float4 v = src[i];
    __nv_bfloat16 h0,l0,h1,l1,h2,l2,h3,l3;
    split2(v.x, h0, l0); split2(v.y, h1, l1);
    split2(v.z, h2, l2); split2(v.w, h3, l3);
    hi[2*i]   = __halves2bfloat162(h0, h1);
    hi[2*i+1] = __halves2bfloat162(h2, h3);
    lo[2*i]   = __halves2bfloat162(l0, l1);
    lo[2*i+1] = __halves2bfloat162(l2, l3);
}

// ------------------------- bf16x3 tensor-core GEMM ---------------------------
// C[m,n] = sum_k A[m,k]*W[n,k] + bias[n].
// A given as (Ah+Al), W as (Wh+Wl) bf16. 3-term product: hh + hl + lh.
// mode 0: f32 out to C.  mode 1: GELU then bf16 hi/lo out.  mode 2: bf16 hi/lo.

__device__ __forceinline__ void cpa16(uint32_t dst, const void* src, int srcsz)
{
    asm volatile("cp.async.ca.shared.global [%0], [%1], 16, %2;"
                 :: "r"(dst), "l"(src), "r"(srcsz));
}
__device__ __forceinline__ void ldmx4(uint32_t& r0, uint32_t& r1,
                                      uint32_t& r2, uint32_t& r3, uint32_t addr)
{
    asm volatile("ldmatrix.sync.aligned.m8n8.x4.shared.b16 {%0,%1,%2,%3}, [%4];"
        : "=r"(r0), "=r"(r1), "=r"(r2), "=r"(r3) : "r"(addr));
}
__device__ __forceinline__ void mma_bf(float* c, const uint32_t* a, const uint32_t* b)
{
    asm volatile("mma.sync.aligned.m16n8k16.row.col.f32.bf16.bf16.f32 "
        "{%0,%1,%2,%3}, {%4,%5,%6,%7}, {%8,%9}, {%0,%1,%2,%3};"
        : "+f"(c[0]), "+f"(c[1]), "+f"(c[2]), "+f"(c[3])
        : "r"(a[0]), "r"(a[1]), "r"(a[2]), "r"(a[3]), "r"(b[0]), "r"(b[1]));
}

// smem: [stage(2)][arr(4: Ah,Al,Wh,Wl)][row(128)][col(40 bf16, 80B stride)]
#define SOFF(s, arr, row, col) (((((s)*4 + (arr))*128 + (row))*40 + (col)))
constexpr int GEMM_SMEM = 2 * 4 * 128 * 40 * 2;   // 81920 bytes

__global__ void __launch_bounds__(256) bf_gemm_kernel(
    const __nv_bfloat16* __restrict__ Ah, const __nv_bfloat16* __restrict__ Al,
    const __nv_bfloat16* __restrict__ Wh, const __nv_bfloat16* __restrict__ Wl,
    const float* __restrict__ bias, float* __restrict__ C,
    __nv_bfloat16* __restrict__ Oh, __nv_bfloat16* __restrict__ Ol,
    int M, int N, int K, int mode)
{
    extern __shared__ __align__(16) __nv_bfloat16 sm[];
    const uint32_t smb = (uint32_t)__cvta_generic_to_shared(sm);

    const int tid  = threadIdx.x;
    const int wid  = tid >> 5;
    const int lane = tid & 31;
    const int wm   = wid >> 2;          // 0..1
    const int wn   = wid & 3;           // 0..3
    const int g    = lane >> 2;
    const int q    = lane & 3;
    const int row0 = blockIdx.y * 128;
    const int col0 = blockIdx.x * 128;

    float acc[4][4][4];
    #pragma unroll
    for (int i = 0; i < 4; i++)
        #pragma unroll
        for (int j = 0; j < 4; j++)
            #pragma unroll
            for (int v = 0; v < 4; v++) acc[i][j][v] = 0.f;

    const int lrow = tid >> 1;          // 0..127
    const int c0b  = (tid & 1) * 2;     // 16B-chunk base {0,2}

    const int T = K / 32;

    auto prefetch = [&](int t, int s) {
        const int k0 = t * 32;
        int gr = row0 + lrow;
        int av = (gr < M) ? 16 : 0;
        int grc = (gr < M) ? gr : 0;
        size_t aoff = (size_t)grc * K + k0;
        size_t boff = (size_t)(col0 + lrow) * K + k0;
        #pragma unroll
        for (int c = c0b; c < c0b + 2; c++) {
            cpa16(smb + SOFF(s, 0, lrow, c*8) * 2, Ah + aoff + c*8, av);
            cpa16(smb + SOFF(s, 1, lrow, c*8) * 2, Al + aoff + c*8, av);
            cpa16(smb + SOFF(s, 2, lrow, c*8) * 2, Wh + boff + c*8, 16);
            cpa16(smb + SOFF(s, 3, lrow, c*8) * 2, Wl + boff + c*8, 16);
        }
        asm volatile("cp.async.commit_group;" ::: "memory");
    };

    prefetch(0, 0);

    for (int t = 0; t < T; t++) {
        const int s = t & 1;
        asm volatile("cp.async.wait_group 0;" ::: "memory");
        __syncthreads();
        if (t + 1 < T) prefetch(t + 1, (t + 1) & 1);

        #pragma unroll
        for (int kh = 0; kh < 32; kh += 16) {
            const int fr = lane & 15;           // row-in-tile
            const int fc = kh + (lane >> 4) * 8;
            uint32_t bh[4][2], bl[4][2];
            #pragma unroll
            for (int pr = 0; pr < 2; pr++) {
                int nr = wn * 32 + pr * 16 + fr;
                uint32_t r0, r1, r2, r3;
                ldmx4(r0, r1, r2, r3, smb + SOFF(s, 2, nr, fc) * 2);
                bh[2*pr][0] = r0; bh[2*pr+1][0] = r1;
                bh[2*pr][1] = r2; bh[2*pr+1][1] = r3;
                ldmx4(r0, r1, r2, r3, smb + SOFF(s, 3, nr, fc) * 2);
                bl[2*pr][0] = r0; bl[2*pr+1][0] = r1;
                bl[2*pr][1] = r2; bl[2*pr+1][1] = r3;
            }
            #pragma unroll
            for (int mt = 0; mt < 4; mt++) {
                int mr = wm * 64 + mt * 16 + fr;
                uint32_t ah[4], al[4];
                ldmx4(ah[0], ah[1], ah[2], ah[3], smb + SOFF(s, 0, mr, fc) * 2);
                ldmx4(al[0], al[1], al[2], al[3], smb + SOFF(s, 1, mr, fc) * 2);
                #pragma unroll
                for (int nt = 0; nt < 4; nt++) {
                    mma_bf(acc[mt][nt], ah, bh[nt]);   // hi*hi
                    mma_bf(acc[mt][nt], ah, bl[nt]);   // hi*lo
                    mma_bf(acc[mt][nt], al, bh[nt]);   // lo*hi
                }
            }
        }
        __syncthreads();
    }

    // epilogue
    #pragma unroll
    for (int mt = 0; mt < 4; mt++) {
        int r0 = row0 + wm * 64 + mt * 16 + g;
        #pragma unroll
        for (int nt = 0; nt < 4; nt++) {
            int cc = col0 + wn * 32 + nt * 8 + 2 * q;
            float b0 = bias[cc], b1 = bias[cc + 1];
            #pragma unroll
            for (int h = 0; h < 2; h++) {
                int r = r0 + 8 * h;
                if (r >= M) continue;
                float v0 = acc[mt][nt][2*h]     + b0;
                float v1 = acc[mt][nt][2*h + 1] + b1;
                if (mode == 0) {
                    *(float2*)&C[(size_t)r * N + cc] = make_float2(v0, v1);
                } else {
                    if (mode == 1) { v0 = v0 * normcdff(v0); v1 = v1 * normcdff(v1); }
                    __nv_bfloat16 h0, l0, h1, l1;
                    split2(v0, h0, l0); split2(v1, h1, l1);
                    *(__nv_bfloat162*)&Oh[(size_t)r * N + cc] = __halves2bfloat162(h0, h1);
                    *(__nv_bfloat162*)&Ol[(size_t)r * N + cc] = __halves2bfloat162(l0, l1);
                }
            }
        }
    }
}

// ------------------------------ LayerNorm -----------------------------------
__device__ __forceinline__ float blk_sum(float v, float* smr)
{
    const int lane = threadIdx.x & 31, w = threadIdx.x >> 5;
    #pragma unroll
    for (int o = 16; o; o >>= 1) v += __shfl_xor_sync(0xffffffffu, v, o);
    if (lane == 0) smr[w] = v;
    __syncthreads();
    if (threadIdx.x == 0) {
        float t = 0.f;
        #pragma unroll
        for (int i = 0; i < 8; i++) t += smr[i];
        smr[8] = t;
    }
    __syncthreads();
    float t = smr[8];
    __syncthreads();
    return t;
}

// LN with fused gather; output split bf16 hi/lo.
// gm 0: in + r*CD.  gm 1: time gather from g_xb.  gm 2: space gather from g_xb.
__global__ void __launch_bounds__(256) ln_hl_kernel(
    const float* __restrict__ in, const float* __restrict__ w,
    const float* __restrict__ b, __nv_bfloat16* __restrict__ oh,
    __nv_bfloat16* __restrict__ ol, int gm)
{
    __shared__ float smr[9];
    const int r = blockIdx.x;
    const float* x;
    if (gm == 0) {
        x = in + (size_t)r * CD;
    } else if (gm == 1) {
        int t = r % TT; int bn = r / TT; int n = bn % NP; int bb = bn / NP;
        x = in + ((size_t)bb * SEQ + 1 + t * NP + n) * CD;
    } else {
        int m = r % KS; int bt = r / KS; int t = bt % TT; int bb = bt / TT;
        x = in + ((m == 0) ? ((size_t)bb * SEQ) * CD
                           : ((size_t)bb * SEQ + 1 + t * NP + (m - 1)) * CD);
    }
    const int t = threadIdx.x;
    float v0 = x[t], v1 = x[t + 256], v2 = x[t + 512];
    float tot = blk_sum(v0 + v1 + v2, smr);
    float mean = tot * (1.0f / CD);
    float d0 = v0 - mean, d1 = v1 - mean, d2 = v2 - mean;
    float tot2 = blk_sum(d0 * d0 + d1 * d1 + d2 * d2, smr);
    float inv = rsqrtf(tot2 * (1.0f / CD) + 1e-6f);
    size_t base = (size_t)r * CD;
    float o0 = d0 * inv * w[t]       + b[t];
    float o1 = d1 * inv * w[t + 256] + b[t + 256];
    float o2 = d2 * inv * w[t + 512] + b[t + 512];
    split2(o0, oh[base + t],       ol[base + t]);
    split2(o1, oh[base + t + 256], ol[base + t + 256]);
    split2(o2, oh[base + t + 512], ol[base + t + 512]);
}

// plain LN, f32 out (final norm for the head)
__global__ void __launch_bounds__(256) ln_kernel(
    const float* __restrict__ in, float* __restrict__ out,
    const float* __restrict__ w, const float* __restrict__ b)
{
    __shared__ float smr[9];
    const size_t r = blockIdx.x;
    const float* x = in + r * CD;
    const int t = threadIdx.x;
    float v0 = x[t], v1 = x[t + 256], v2 = x[t + 512];
    float tot = blk_sum(v0 + v1 + v2, smr);
    float mean = tot * (1.0f / CD);
    float d0 = v0 - mean, d1 = v1 - mean, d2 = v2 - mean;
    float tot2 = blk_sum(d0 * d0 + d1 * d1 + d2 * d2, smr);
    float inv = rsqrtf(tot2 * (1.0f / CD) + 1e-6f);
    float* o = out + r * CD;
    o[t]       = d0 * inv * w[t]       + b[t];
    o[t + 256] = d1 * inv * w[t + 256] + b[t + 256];
    o[t + 512] = d2 * inv * w[t + 512] + b[t + 512];
}

// ------------------------- Time attention (seq=8) ---------------------------
__global__ void __launch_bounds__(64) time_attn_kernel()
{
    const int g = blockIdx.x;
    const int h = g % NH;
    const int bn = g / NH;
    const int lane = threadIdx.x;
    __shared__ float Q[TT][HD + 1], Kk[TT][HD + 1], V[TT][HD + 1];
    __shared__ float P[TT][TT + 1];
    #pragma unroll
    for (int t = 0; t < TT; t++) {
        size_t base = ((size_t)(bn * TT + t)) * (3 * CD) + h * HD + lane;
        Q[t][lane]  = g_qkv[base];
        Kk[t][lane] = g_qkv[base + CD];
        V[t][lane]  = g_qkv[base + 2 * CD];
    }
    __syncthreads();
    const int tq = lane >> 3, tk = lane & 7;
    float s = 0.f;
    #pragma unroll
    for (int d = 0; d < HD; d++) s += Q[tq][d] * Kk[tk][d];
    P[tq][tk] = s * 0.125f;
    __syncthreads();
    if (lane < TT) {
        float m = -1e30f;
        #pragma unroll
        for (int k = 0; k < TT; k++) m = fmaxf(m, P[lane][k]);
        float sum = 0.f;
        #pragma unroll
        for (int k = 0; k < TT; k++) { float e = expf(P[lane][k] - m); P[lane][k] = e; sum += e; }
        float inv = 1.f / sum;
        #pragma unroll
        for (int k = 0; k < TT; k++) P[lane][k] *= inv;
    }
    __syncthreads();
    #pragma unroll
    for (int t = 0; t < TT; t++) {
        float a = 0.f;
        #pragma unroll
        for (int k = 0; k < TT; k++) a += P[t][k] * V[k][lane];
        size_t idx = ((size_t)(bn * TT + t)) * CD + h * HD + lane;
        split2(a, g_at_hi[idx], g_at_lo[idx]);
    }
}

// ------------------------- Space attention (seq=197) ------------------------
__global__ void __launch_bounds__(256) space_scores_kernel()
{
    const int g = blockIdx.x;
    const int h = g % NH, bt = g / NH;
    const int q0 = blockIdx.y * 32, k0 = blockIdx.z * 64;
    __shared__ float Qs[32][HD + 1];
    __shared__ float Ksm[64][HD + 1];
    const int tid = threadIdx.x;
    for (int i = tid; i < 32 * 64; i += 256) {
        int r = i >> 6, d = i & 63; int gq = q0 + r;
        Qs[r][d] = (gq < KS) ? g_qkv[((size_t)(bt * KS + gq)) * (3 * CD) + h * HD + d] : 0.f;
    }
    for (int i = tid; i < 64 * 64; i += 256) {
        int r = i >> 6, d = i & 63; int gk = k0 + r;
        Ksm[r][d] = (gk < KS) ? g_qkv[((size_t)(bt * KS + gk)) * (3 * CD) + CD + h * HD + d] : 0.f;
    }
    __syncthreads();
    const int kc = tid & 63, qb = tid >> 6;
    float s[8];
    #pragma unroll
    for (int i = 0; i < 8; i++) s[i] = 0.f;
    #pragma unroll
    for (int d = 0; d < HD; d++) {
        float kv = Ksm[kc][d];
        #pragma unroll
        for (int i = 0; i < 8; i++) s[i] = fmaf(Qs[qb + 4 * i][d], kv, s[i]);
    }
    const int gk = k0 + kc;
    if (gk < KS) {
        #pragma unroll
        for (int i = 0; i < 8; i++) {
            int gq = q0 + qb + 4 * i;
            if (gq < KS) g_scores[((size_t)g * KS + gq) * KS + gk] = s[i] * 0.125f;
        }
    }
}

__global__ void __launch_bounds__(32) softmax197_kernel()
{
    const size_t row = blockIdx.x;
    float* p = g_scores + row * KS;
    const int lane = threadIdx.x;
    float vals[7];
    float m = -1e30f;
    #pragma unroll
    for (int i = 0; i < 7; i++) {
        int j = lane + 32 * i;
        vals[i] = (j < KS) ? p[j] : -1e30f;
        m = fmaxf(m, vals[i]);
    }
    #pragma unroll
    for (int o = 16; o; o >>= 1) m = fmaxf(m, __shfl_xor_sync(0xffffffffu, m, o));
    float s = 0.f;
    #pragma unroll
    for (int i = 0; i < 7; i++) {
        int j = lane + 32 * i;
        if (j < KS) { vals[i] = expf(vals[i] - m); s += vals[i]; }
    }
    #pragma unroll
    for (int o = 16; o; o >>= 1) s += __shfl_xor_sync(0xffffffffu, s, o);
    float inv = 1.f / s;
    #pragma unroll
    for (int i = 0; i < 7; i++) {
        int j = lane + 32 * i;
        if (j < KS) p[j] = vals[i] * inv;
    }
}

__global__ void __launch_bounds__(256) space_pv_kernel()
{
    const int g = blockIdx.x;
    const int h = g % NH, bt = g / NH;
    const int q0 = blockIdx.y * 32;
    __shared__ float Ps[32][33];
    __shared__ float Vs[32][HD + 1];
    const int tid = threadIdx.x;
    const int dc = tid & 63, qb = tid >> 6;
    float acc[8];
    #pragma unroll
    for (int i = 0; i < 8; i++) acc[i] = 0.f;
    for (int c0 = 0; c0 < KS; c0 += 32) {
        for (int i = tid; i < 32 * 32; i += 256) {
            int r = i >> 5, c = i & 31; int gq = q0 + r, gk = c0 + c;
            Ps[r][c] = (gq < KS && gk < KS) ? g_scores[((size_t)g * KS + gq) * KS + gk] : 0.f;
        }
        for (int i = tid; i < 32 * 64; i += 256) {
            int r = i >> 6, d = i & 63; int gk = c0 + r;
            Vs[r][d] = (gk < KS) ? g_qkv[((size_t)(bt * KS + gk)) * (3 * CD) + 2 * CD + h * HD + d] : 0.f;
        }
        __syncthreads();
        #pragma unroll
        for (int kk = 0; kk < 32; kk++) {
            float vv = Vs[kk][dc];
            #pragma unroll
            for (int i = 0; i < 8; i++) acc[i] = fmaf(Ps[qb + 4 * i][kk], vv, acc[i]);
        }
        __syncthreads();
    }
    #pragma unroll
    for (int i = 0; i < 8; i++) {
        int gq = q0 + qb + 4 * i;
        if (gq < KS) {
            size_t idx = ((size_t)(bt * KS + gq)) * CD + h * HD + dc;
            split2(acc[i], g_at_hi[idx], g_at_lo[idx]);
        }
    }
}

// --------------------------- elementwise helpers ----------------------------
__global__ void patchify_kernel(const float* __restrict__ x)
{
    int i = blockIdx.x * blockDim.x + threadIdx.x;
    if (i >= RT * CD) return;
    int k = i % CD; int r = i / CD;
    int n = r % NP; int bt = r / NP; int t = bt % TT; int b = bt / TT;
    int ci = k >> 8; int rem = k & 255; int py = rem >> 4; int px = rem & 15;
    int nh = n / 14, nw = n % 14;
    size_t src = ((((size_t)b * 3 + ci) * TT + t) * 224 + (nh * 16 + py)) * 224 + (nw * 16 + px);
    split2(x[src], g_pa_hi[i], g_pa_lo[i]);
}

__global__ void init_cls_kernel(const float* __restrict__ cls_token,
                                const float* __restrict__ pos_embed)
{
    int i = blockIdx.x * blockDim.x + threadIdx.x;
    if (i >= BATCH * CD) return;
    int b = i / CD, c = i % CD;
    g_xb[((size_t)b * SEQ) * CD + c] = cls_token[c] + pos_embed[c];
}

__global__ void init_patch_kernel(const float* __restrict__ pos_embed,
                                  const float* __restrict__ time_embed)
{
    int i = blockIdx.x * blockDim.x + threadIdx.x;
    if (i >= RT * CD) return;
    int c = i % CD; int r = i / CD;
    int n = r % NP; int bt = r / NP; int t = bt % TT; int b = bt / TT;
    g_xb[((size_t)b * SEQ + 1 + t * NP + n) * CD + c] =
        g_buf3[i] + pos_embed[(size_t)(1 + n) * CD + c] + time_embed[(size_t)t * CD + c];
}

__global__ void scatter_time_kernel()
{
    int i = blockIdx.x * blockDim.x + threadIdx.x;
    if (i >= RT * CD) return;
    int c = i % CD; int r = i / CD;
    int t = r % TT; int bn = r / TT; int n = bn % NP; int b = bn / NP;
    g_xb[((size_t)b * SEQ + 1 + t * NP + n) * CD + c] += g_buf1[i];
}

__global__ void combine_space_kernel()
{
    int i = blockIdx.x * blockDim.x + threadIdx.x;
    if (i >= RT * CD) return;
    int c = i % CD; int r = i / CD;
    int n = r % NP; int bt = r / NP; int t = bt % TT; int b = bt / TT;
    g_xb[((size_t)b * SEQ + 1 + t * NP + n) * CD + c] +=
        g_buf3[((size_t)(bt * KS + 1 + n)) * CD + c];
}

__global__ void combine_cls_kernel()
{
    int i = blockIdx.x * blockDim.x + threadIdx.x;
    if (i >= BATCH * CD) return;
    int b = i / CD, c = i % CD;
    float s = 0.f;
    #pragma unroll
    for (int t = 0; t < TT; t++)
        s += g_buf3[((size_t)((b * TT + t) * KS)) * CD + c];
    g_xb[((size_t)b * SEQ) * CD + c] += s * (1.f / TT);
}

__global__ void add_residual_kernel()
{
    int i = blockIdx.x * blockDim.x + threadIdx.x;
    if (i >= RX * CD) return;
    g_xb[i] += g_buf3[i];
}

// ------------------------------- head ---------------------------------------
__global__ void __launch_bounds__(256) head_kernel(
    const float* __restrict__ hw, const float* __restrict__ hb,
    float* __restrict__ out)
{
    const int warp = threadIdx.x >> 5, lane = threadIdx.x & 31;
    const int o = blockIdx.x * 8 + warp;
    if (o >= BATCH * 1000) return;
    const int b = o / 1000, j = o % 1000;
    const float* xr = g_buf2 + (size_t)b * SEQ * CD;
    const float* wr = hw + (size_t)j * CD;
    float s = 0.f;
    for (int k = lane; k < CD; k += 32) s += xr[k] * wr[k];
    #pragma unroll
    for (int off = 16; off; off >>= 1) s += __shfl_down_sync(0xffffffffu, s, off);
    if (lane == 0) out[o] = s + hb[j];
}

// ------------------------------ launcher ------------------------------------
static inline int cdiv(int a, int b) { return (a + b - 1) / b; }

struct WB { __nv_bfloat16 *hi, *lo; };

static void gemm_bf(const __nv_bfloat16* Ah, const __nv_bfloat16* Al,
                    const __nv_bfloat16* Wh, const __nv_bfloat16* Wl,
                    const float* bias, float* C,
                    __nv_bfloat16* Oh, __nv_bfloat16* Ol,
                    int M, int N, int K, int mode)
{
    dim3 gr(N / 128, cdiv(M, 128));
    bf_gemm_kernel<<<gr, 256, GEMM_SMEM>>>(Ah, Al, Wh, Wl, bias, C, Oh, Ol,
                                           M, N, K, mode);
}

static void wsplit(const float* src, __nv_bfloat16* hi, __nv_bfloat16* lo, size_t n)
{
    long n4 = (long)(n / 4);
    wsplit_kernel<<<(int)((n4 + 255) / 256), 256>>>(
        (const float4*)src, (__nv_bfloat162*)hi, (__nv_bfloat162*)lo, n4);
}

extern "C" void kernel_launch(void* const* d_in, const int* in_sizes, int n_in,
                              void* d_out, int out_size)
{
    const float* x          = (const float*)d_in[0];
    const float* conv_w     = (const float*)d_in[1];
    const float* conv_b     = (const float*)d_in[2];
    const float* cls_token  = (const float*)d_in[3];
    const float* pos_embed  = (const float*)d_in[4];
    const float* time_embed = (const float*)d_in[5];
    const float* tn_w   = (const float*)d_in[6];
    const float* tn_b   = (const float*)d_in[7];
    const float* tqkv_w = (const float*)d_in[8];
    const float* tqkv_b = (const float*)d_in[9];
    const float* tproj_w= (const float*)d_in[10];
    const float* tproj_b= (const float*)d_in[11];
    const float* tfc_w  = (const float*)d_in[12];
    const float* tfc_b  = (const float*)d_in[13];
    const float* n1_w   = (const float*)d_in[14];
    const float* n1_b   = (const float*)d_in[15];
    const float* sqkv_w = (const float*)d_in[16];
    const float* sqkv_b = (const float*)d_in[17];
    const float* sproj_w= (const float*)d_in[18];
    const float* sproj_b= (const float*)d_in[19];
    const float* n2_w   = (const float*)d_in[20];
    const float* n2_b   = (const float*)d_in[21];
    const float* fc1_w  = (const float*)d_in[22];
    const float* fc1_b  = (const float*)d_in[23];
    const float* fc2_w  = (const float*)d_in[24];
    const float* fc2_b  = (const float*)d_in[25];
    const float* norm_w = (const float*)d_in[26];
    const float* norm_b = (const float*)d_in[27];
    const float* head_w = (const float*)d_in[28];
    const float* head_b = (const float*)d_in[29];

    float *xb, *buf1, *buf2, *buf3, *qkv;
    cudaGetSymbolAddress((void**)&xb,   g_xb);
    cudaGetSymbolAddress((void**)&buf1, g_buf1);
    cudaGetSymbolAddress((void**)&buf2, g_buf2);
    cudaGetSymbolAddress((void**)&buf3, g_buf3);
    cudaGetSymbolAddress((void**)&qkv,  g_qkv);

    __nv_bfloat16 *whi, *wlo, *lnh, *lnl, *ath, *atl, *f1h, *f1l, *pah, *pal;
    cudaGetSymbolAddress((void**)&whi, g_w_hi);
    cudaGetSymbolAddress((void**)&wlo, g_w_lo);
    cudaGetSymbolAddress((void**)&lnh, g_ln_hi);
    cudaGetSymbolAddress((void**)&lnl, g_ln_lo);
    cudaGetSymbolAddress((void**)&ath, g_at_hi);
    cudaGetSymbolAddress((void**)&atl, g_at_lo);
    cudaGetSymbolAddress((void**)&f1h, g_f1_hi);
    cudaGetSymbolAddress((void**)&f1l, g_f1_lo);
    cudaGetSymbolAddress((void**)&pah, g_pa_hi);
    cudaGetSymbolAddress((void**)&pal, g_pa_lo);

    cudaFuncSetAttribute(bf_gemm_kernel,
                         cudaFuncAttributeMaxDynamicSharedMemorySize, GEMM_SMEM);

    const int EB = 256;

    // ---- split all weights into bf16 hi/lo ----
    wsplit(tqkv_w,  whi + W_TQKV,  wlo + W_TQKV,  SZ_TQKV);
    wsplit(tproj_w, whi + W_TPROJ, wlo + W_TPROJ, SZ_CC);
    wsplit(tfc_w,   whi + W_TFC,   wlo + W_TFC,   SZ_CC);
    wsplit(sqkv_w,  whi + W_SQKV,  wlo + W_SQKV,  SZ_TQKV);
    wsplit(sproj_w, whi + W_SPROJ, wlo + W_SPROJ, SZ_CC);
    wsplit(fc1_w,   whi + W_FC1,   wlo + W_FC1,   SZ_FC);
    wsplit(fc2_w,   whi + W_FC2,   wlo + W_FC2,   SZ_FC);
    wsplit(conv_w,  whi + W_CONV,  wlo + W_CONV,  (size_t)CD * CD);

    // ---- patch embedding + pos/time embed + cls init ----
    patchify_kernel<<<cdiv(RT * CD, EB), EB>>>(x);
    gemm_bf(pah, pal, whi + W_CONV, wlo + W_CONV, conv_b, buf3, nullptr, nullptr,
            RT, CD, CD, 0);
    init_cls_kernel<<<cdiv(BATCH * CD, EB), EB>>>(cls_token, pos_embed);
    init_patch_kernel<<<cdiv(RT * CD, EB), EB>>>(pos_embed, time_embed);

    // ---- transformer blocks ----
    for (int l = 0; l < DEPTH; l++) {
        size_t o3 = (size_t)l * 3 * CD * CD;
        size_t o1 = (size_t)l * CD * CD;
        size_t o4 = (size_t)l * 4 * CD * CD;

        // ===== time attention =====
        ln_hl_kernel<<<RT, 256>>>(xb, tn_w + (size_t)l * CD, tn_b + (size_t)l * CD,
                                  lnh, lnl, 1);
        gemm_bf(lnh, lnl, whi + W_TQKV + o3, wlo + W_TQKV + o3,
                tqkv_b + (size_t)l * 3 * CD, qkv, nullptr, nullptr,
                RT, 3 * CD, CD, 0);
        time_attn_kernel<<<(RT / TT) * NH, 64>>>();
        gemm_bf(ath, atl, whi + W_TPROJ + o1, wlo + W_TPROJ + o1,
                tproj_b + (size_t)l * CD, nullptr, f1h, f1l,
                RT, CD, CD, 2);
        gemm_bf(f1h, f1l, whi + W_TFC + o1, wlo + W_TFC + o1,
                tfc_b + (size_t)l * CD, buf1, nullptr, nullptr,
                RT, CD, CD, 0);
        scatter_time_kernel<<<cdiv(RT * CD, EB), EB>>>();

        // ===== space attention =====
        ln_hl_kernel<<<RS, 256>>>(xb, n1_w + (size_t)l * CD, n1_b + (size_t)l * CD,
                                  lnh, lnl, 2);
        gemm_bf(lnh, lnl, whi + W_SQKV + o3, wlo + W_SQKV + o3,
                sqkv_b + (size_t)l * 3 * CD, qkv, nullptr, nullptr,
                RS, 3 * CD, CD, 0);
        {
            dim3 gr(GROUPS, cdiv(KS, 32), cdiv(KS, 64));
            space_scores_kernel<<<gr, 256>>>();
        }
        softmax197_kernel<<<GROUPS * KS, 32>>>();
        {
            dim3 gr(GROUPS, cdiv(KS, 32));
            space_pv_kernel<<<gr, 256>>>();
        }
        gemm_bf(ath, atl, whi + W_SPROJ + o1, wlo + W_SPROJ + o1,
                sproj_b + (size_t)l * CD, buf3, nullptr, nullptr,
                RS, CD, CD, 0);
        combine_space_kernel<<<cdiv(RT * CD, EB), EB>>>();
        combine_cls_kernel<<<cdiv(BATCH * CD, EB), EB>>>();

        // ===== MLP =====
        ln_hl_kernel<<<RX, 256>>>(xb, n2_w + (size_t)l * CD, n2_b + (size_t)l * CD,
                                  lnh, lnl, 0);
        gemm_bf(lnh, lnl, whi + W_FC1 + o4, wlo + W_FC1 + o4,
                fc1_b + (size_t)l * 4 * CD, nullptr, f1h, f1l,
                RX, 4 * CD, CD, 1);
        gemm_bf(f1h, f1l, whi + W_FC2 + o4, wlo + W_FC2 + o4,
                fc2_b + (size_t)l * CD, buf3, nullptr, nullptr,
                RX, CD, 4 * CD, 0);
        add_residual_kernel<<<cdiv(RX * CD, EB), EB>>>();
    }

    // ---- final norm + head ----
    ln_kernel<<<RX, 256>>>(xb, buf2, norm_w, norm_b);
    head_kernel<<<cdiv(BATCH * 1000, 8), 256>>>(head_w, head_b, (float*)d_out);
}